// round 6
// baseline (speedup 1.0000x reference)
#include <cuda_runtime.h>
#include <cuda_fp16.h>
#include <math.h>
#include <stdint.h>

// Problem constants
#define NB 2
#define NC 128
#define FH 80
#define FW 80
#define HS 40            // downsampled H=W
#define NQ 1600          // HS*HS
#define NEPS 0.1152f     // 1152 * EPS
#define SCL 10.0f
#define MROWS 2048       // NC * 16 offsets

// fp16 mma GEMM2 config: CTA 128x128, K-tile 32 halfs, 8 warps (warp tile 64x32)
#define KT 32
#define G2_SMEM 32768    // 2 buffers x (8KB A + 8KB B)

// Static scratch (allocation-free rule: __device__ globals)
__device__ float  g_ds[NB*3*NC*NQ];          // downsampled [b][img: 0=l,1=r,2=m][c][q]
__device__ float  g_E[NB*2*NQ];              // per-pixel channel sum of squares (l, r)
__device__ float  g_ninv[NB*2*NQ];           // 1/patch-norm
__device__ float  g_smax[NB*2*NQ];           // softmax max per (bs,p)
__device__ float  g_sinv[NB*2*NQ];           // softmax 1/sum per (bs,p)
__device__ float  g_bufA[NB*2*NQ*NQ];        // 41.9 MB (pixcorr)
__device__ float  g_bufB[NB*2*NQ*NQ];        // 41.9 MB (post-psfuse scores)
__device__ __align__(16) __half g_Gh[NB*2*MROWS*NQ];   // 26 MB paste operand [bs][m][q]
__device__ __align__(16) __half g_ATh[NB*2*NQ*NQ];     // 20.5 MB attnT [bs][p][q]
__device__ float  g_T[NB*2*MROWS*NQ];        // 52.4 MB paste result [bs][m][p]

// ---------------------------------------------------------------- downsample
__global__ void k_downsample(const float* __restrict__ left,
                             const float* __restrict__ right,
                             const float* __restrict__ mid) {
    int idx = blockIdx.x * blockDim.x + threadIdx.x;
    const int total = NB*3*NC*NQ;
    if (idx >= total) return;
    int q = idx % NQ;
    int t = idx / NQ;
    int c = t % NC; t /= NC;
    int img = t % 3; int b = t / 3;
    const float* src = (img == 0) ? left : (img == 1 ? right : mid);
    int qh = q / HS, qw = q % HS;
    g_ds[idx] = src[(size_t)((b*NC + c)*FH + 2*qh)*FW + 2*qw];
}

// ------------------------------------------------- channel sum-of-squares (l,r)
__global__ void k_sumsq() {
    int idx = blockIdx.x*blockDim.x + threadIdx.x;
    const int total = NB*2*NQ;
    if (idx >= total) return;
    int q = idx % NQ; int t = idx / NQ;
    int s = t % 2; int b = t / 2;
    const float* p = g_ds + (size_t)(b*3 + s)*NC*NQ + q;
    float acc = 0.f;
    #pragma unroll 8
    for (int c = 0; c < NC; ++c) { float v = p[(size_t)c*NQ]; acc += v*v; }
    g_E[idx] = acc;
}

// -------------------------------------------------- patch norm
__global__ void k_norm() {
    int idx = blockIdx.x*blockDim.x + threadIdx.x;
    const int total = NB*2*NQ;
    if (idx >= total) return;
    int q = idx % NQ; int bs = idx / NQ;
    int qh = q/HS, qw = q%HS;
    float acc = NEPS;
    for (int di=-1; di<=1; ++di) {
        int h = qh+di; if (h < 0 || h >= HS) continue;
        for (int dj=-1; dj<=1; ++dj) {
            int w = qw+dj; if (w < 0 || w >= HS) continue;
            acc += g_E[bs*NQ + h*HS + w];
        }
    }
    g_ninv[idx] = rsqrtf(acc);
}

// ----------------------------- GEMM1 (fp32): PixCorr[q,p] = sum_c L[c,q]*M[c,p]
__global__ void k_gemm1() {
    int bs = blockIdx.z;
    int b = bs >> 1, s = bs & 1;
    const float* A  = g_ds + (size_t)(b*3 + s)*NC*NQ;
    const float* Bm = g_ds + (size_t)(b*3 + 2)*NC*NQ;
    float* Cout = g_bufA + (size_t)bs*NQ*NQ;
    __shared__ float As[16][64];
    __shared__ float Bs[16][64];
    int tx = threadIdx.x;
    int m0 = blockIdx.x*64, n0 = blockIdx.y*64;
    int lk = tx >> 4, lm = (tx & 15) * 4;
    int lr = tx >> 4, lc = tx & 15;
    float acc[4][4];
    #pragma unroll
    for (int i=0;i<4;i++)
        #pragma unroll
        for (int j=0;j<4;j++) acc[i][j] = 0.f;
    for (int k0 = 0; k0 < NC; k0 += 16) {
        *(float4*)&As[lk][lm] = *(const float4*)&A [(size_t)(k0+lk)*NQ + m0 + lm];
        *(float4*)&Bs[lk][lm] = *(const float4*)&Bm[(size_t)(k0+lk)*NQ + n0 + lm];
        __syncthreads();
        #pragma unroll
        for (int kk = 0; kk < 16; ++kk) {
            float4 av = *(const float4*)&As[kk][lr*4];
            float4 bv = *(const float4*)&Bs[kk][lc*4];
            float a[4] = {av.x, av.y, av.z, av.w};
            float bb[4] = {bv.x, bv.y, bv.z, bv.w};
            #pragma unroll
            for (int i=0;i<4;i++)
                #pragma unroll
                for (int j=0;j<4;j++) acc[i][j] += a[i]*bb[j];
        }
        __syncthreads();
    }
    #pragma unroll
    for (int i=0;i<4;i++) {
        float4 v = make_float4(acc[i][0],acc[i][1],acc[i][2],acc[i][3]);
        *(float4*)&Cout[(size_t)(m0+lr*4+i)*NQ + n0 + lc*4] = v;
    }
}

// -------- FUSED patchsum + fuse1, 4 outputs per thread (bufA -> bufB)
__global__ void k_psfuse() {
    int idx = blockIdx.x*blockDim.x + threadIdx.x;
    const int total4 = NB*2*NQ*(NQ/4);
    if (idx >= total4) return;
    int p4 = (idx % (NQ/4)) * 4;
    int t = idx / (NQ/4);
    int q = t % NQ;
    int bs = t / NQ;
    const float* __restrict__ Cm = g_bufA + (size_t)bs*NQ*NQ;
    const float* __restrict__ ninv = g_ninv + bs*NQ;
    const int qh = q/HS, qw = q - (q/HS)*HS;
    const int ph0 = p4/HS, pw0 = p4 - (p4/HS)*HS;   // pw0 in [0,36], 4-aligned
    float acc[4] = {0.f,0.f,0.f,0.f};

    #pragma unroll
    for (int ei = 0; ei < 3; ++ei) {
        const int e = (ei==0) ? 0 : (ei==1 ? -1 : 1);
        const int Q = q + e;
        if (Q < 0 || Q >= NQ) continue;
        int Qh = qh, Qw = qw + e;
        if (Qw < 0) { Qh -= 1; Qw = HS-1; }
        else if (Qw >= HS) { Qh += 1; Qw = 0; }
        const float nv = ninv[Q];
        // per-element P coordinates (only edges can carry/borrow)
        int Pj[4], Phj[4], Pwj[4]; bool Vj[4];
        #pragma unroll
        for (int j = 0; j < 4; ++j) {
            int P = p4 + e + j;
            int Pw = pw0 + e + j, Ph = ph0;
            if (Pw < 0) { Ph -= 1; Pw = HS-1; }
            else if (Pw >= HS) { Ph += 1; Pw = 0; }
            Pj[j] = P; Phj[j] = Ph; Pwj[j] = Pw;
            Vj[j] = (P >= 0) && (P < NQ);
        }
        float ps[4] = {0.f,0.f,0.f,0.f};
        #pragma unroll
        for (int di = -1; di <= 1; ++di) {
            int Qhd = Qh + di;
            if (Qhd < 0 || Qhd >= HS) continue;
            #pragma unroll
            for (int dj = -1; dj <= 1; ++dj) {
                int Qwd = Qw + dj;
                if (Qwd < 0 || Qwd >= HS) continue;
                int sh = di*HS + dj;
                const float* row = Cm + (size_t)(Q + sh)*NQ;
                #pragma unroll
                for (int j = 0; j < 4; ++j) {
                    int Phd = Phj[j] + di, Pwd = Pwj[j] + dj;
                    if (Vj[j] && Phd >= 0 && Phd < HS && Pwd >= 0 && Pwd < HS)
                        ps[j] += row[Pj[j] + sh];
                }
            }
        }
        #pragma unroll
        for (int j = 0; j < 4; ++j) acc[j] += ps[j] * nv;
    }
    *(float4*)&g_bufB[((size_t)(bs*NQ + q))*NQ + p4] =
        make_float4(acc[0], acc[1], acc[2], acc[3]);
}

// fuse2 tap helpers: qa- = tflat(tflat(q)-1), qa+ = tflat(tflat(q)+1)
// (closed forms; valid- iff idx>0, valid+ iff idx<NQ-1)
__device__ __forceinline__ int f2_minus(int v, int vh, int vw) {
    return (vh > 0) ? (v - HS) : ((HS-1)*HS + vw - 1);
}
__device__ __forceinline__ int f2_plus(int v, int vh, int vw) {
    return (vh < HS-1) ? (v + HS) : (vw + 1);
}

// --------------- softmax stats with fuse2 on the fly (reads bufB)
__global__ void k_softmax_stats() {
    int bs = blockIdx.y;
    int p0 = blockIdx.x * 64;
    const float* __restrict__ F = g_bufB + (size_t)bs*NQ*NQ;
    int px = threadIdx.x & 63;
    int qy = threadIdx.x >> 6;        // 0..3
    int p = p0 + px;
    const int ph = p/HS, pw = p - (p/HS)*HS;
    const int pbm = f2_minus(p, ph, pw);
    const int pbp = f2_plus(p, ph, pw);
    const bool pmok = (p > 0), ppok = (p < NQ-1);
    __shared__ float red[4][64];

    // pass 1: max
    float mx = -3.4e38f;
    {
        int qh = 0, qw = qy;
        for (int q = qy; q < NQ; q += 4) {
            float v = F[(size_t)q*NQ + p];
            if (pmok && q > 0)    v += F[(size_t)f2_minus(q, qh, qw)*NQ + pbm];
            if (ppok && q < NQ-1) v += F[(size_t)f2_plus(q, qh, qw)*NQ + pbp];
            mx = fmaxf(mx, v);
            qw += 4; if (qw >= HS) { qw -= HS; qh += 1; }
        }
    }
    red[qy][px] = mx;
    __syncthreads();
    mx = fmaxf(fmaxf(red[0][px], red[1][px]), fmaxf(red[2][px], red[3][px]));
    __syncthreads();

    // pass 2: sum of exp
    float sm = 0.f;
    {
        int qh = 0, qw = qy;
        for (int q = qy; q < NQ; q += 4) {
            float v = F[(size_t)q*NQ + p];
            if (pmok && q > 0)    v += F[(size_t)f2_minus(q, qh, qw)*NQ + pbm];
            if (ppok && q < NQ-1) v += F[(size_t)f2_plus(q, qh, qw)*NQ + pbp];
            sm += __expf(SCL * (v - mx));
            qw += 4; if (qw >= HS) { qw -= HS; qh += 1; }
        }
    }
    red[qy][px] = sm;
    __syncthreads();
    if (qy == 0) {
        g_smax[bs*NQ + p] = mx;
        g_sinv[bs*NQ + p] = 1.0f / (red[0][px] + red[1][px] + red[2][px] + red[3][px]);
    }
}

// --------------- attnT with fuse2 on the fly: (bufB -> g_ATh transposed half)
__global__ void k_attnT() {
    __shared__ float tile[32][33];
    int bs = blockIdx.z;
    int q0 = blockIdx.x * 32, p0 = blockIdx.y * 32;
    const float* __restrict__ F = g_bufB + (size_t)bs*NQ*NQ;
    __half* __restrict__ O = g_ATh + (size_t)bs*NQ*NQ;
    int tx = threadIdx.x, ty = threadIdx.y;  // 32 x 8
    int p = p0 + tx;
    const int ph = p/HS, pw = p - (p/HS)*HS;
    const int pbm = f2_minus(p, ph, pw);
    const int pbp = f2_plus(p, ph, pw);
    const bool pmok = (p > 0), ppok = (p < NQ-1);
    for (int r = ty; r < 32; r += 8) {
        int q = q0 + r;
        int qh = q/HS, qw = q - (q/HS)*HS;
        float v = F[(size_t)q*NQ + p];
        if (pmok && q > 0)    v += F[(size_t)f2_minus(q, qh, qw)*NQ + pbm];
        if (ppok && q < NQ-1) v += F[(size_t)f2_plus(q, qh, qw)*NQ + pbp];
        tile[r][tx] = v;
    }
    __syncthreads();
    for (int r = ty; r < 32; r += 8) {
        int pp = p0 + r;
        float e = __expf(SCL * (tile[tx][r] - g_smax[bs*NQ + pp])) * g_sinv[bs*NQ + pp];
        O[(size_t)pp*NQ + q0 + tx] = __float2half_rn(e);
    }
}

// --------------- build paste operand G[bs][m][q] as half, 8 q per thread
__global__ void k_buildG(const float* __restrict__ raw_left,
                         const float* __restrict__ raw_right) {
    int idx = blockIdx.x*blockDim.x + threadIdx.x;
    const int total8 = NB*2*MROWS*(NQ/8);
    if (idx >= total8) return;
    int q8 = (idx % (NQ/8)) * 8;
    int t = idx / (NQ/8);
    int m = t % MROWS;
    int bs = t / MROWS;
    int b = bs >> 1, s = bs & 1;
    int c = m >> 4;
    int o = m & 15;
    int dy = (o >> 2) - 1, dx = (o & 3) - 1;
    int qh = q8 / HS, qw0 = q8 - (q8/HS)*HS;   // 8 consecutive q share the row
    int y = 2*qh + dy;
    const float* raw = (s ? raw_right : raw_left) + (size_t)(b*NC + c)*FH*FW;
    __half hv[8];
    if (y >= 0 && y < FH) {
        const float* rrow = raw + (size_t)y*FW;
        #pragma unroll
        for (int j = 0; j < 8; ++j) {
            int x = 2*(qw0 + j) + dx;
            hv[j] = (x >= 0 && x < FW) ? __float2half_rn(rrow[x]) : __half(0.f);
        }
    } else {
        #pragma unroll
        for (int j = 0; j < 8; ++j) hv[j] = __half(0.f);
    }
    *(uint4*)&g_Gh[(size_t)(bs*MROWS + m)*NQ + q8] = *(uint4*)hv;
}

// ------------- GEMM2 (mma.sync fp16, f32 accum): T[m,p] = sum_q G[m,q] * attnT[p,q]
__device__ __forceinline__ void mma_f16(float* c, uint32_t a0, uint32_t a1,
                                        uint32_t a2, uint32_t a3,
                                        uint32_t b0, uint32_t b1) {
    asm volatile(
        "mma.sync.aligned.m16n8k16.row.col.f32.f16.f16.f32 "
        "{%0,%1,%2,%3}, {%4,%5,%6,%7}, {%8,%9}, {%0,%1,%2,%3};"
        : "+f"(c[0]), "+f"(c[1]), "+f"(c[2]), "+f"(c[3])
        : "r"(a0), "r"(a1), "r"(a2), "r"(a3), "r"(b0), "r"(b1));
}

__global__ void __launch_bounds__(256) k_gemm2h() {
    extern __shared__ char smx[];
    const int bs = blockIdx.z;
    const __half* __restrict__ Gm = g_Gh  + (size_t)bs*MROWS*NQ;   // [m][q]
    const __half* __restrict__ Bm = g_ATh + (size_t)bs*NQ*NQ;      // [p][q]
    float* __restrict__ Tm = g_T + (size_t)bs*MROWS*NQ;
    const int m0 = blockIdx.x * 128, n0 = blockIdx.y * 128;
    const int t = threadIdx.x;
    const int lane = t & 31, wid = t >> 5;
    const int wm = wid & 1, wn = wid >> 1;      // warp grid 2(m) x 4(n)

    const int prow = t >> 1, ps = t & 1;
    const int pmt = prow >> 4, prr = prow & 15;
    const int pgA = prr & 7;
    const int hwA = (prr >> 3) << 3;
    const int pnt = prow >> 3, pgB = prow & 7;
    const bool pBvalid = (n0 + prow) < NQ;

    uint32_t al[4], ah[4], bl[4], bh[4];

    float acc[4][4][4];
    #pragma unroll
    for (int i=0;i<4;i++)
        #pragma unroll
        for (int j=0;j<4;j++)
            #pragma unroll
            for (int k=0;k<4;k++) acc[i][j][k] = 0.f;

    {
        const uint4* pa = (const uint4*)(Gm + (size_t)(m0+prow)*NQ + ps*16);
        uint4 lo = pa[0], hi = pa[1];
        al[0]=lo.x; al[1]=lo.y; al[2]=lo.z; al[3]=lo.w;
        ah[0]=hi.x; ah[1]=hi.y; ah[2]=hi.z; ah[3]=hi.w;
        if (pBvalid) {
            const uint4* pb = (const uint4*)(Bm + (size_t)(n0+prow)*NQ + ps*16);
            uint4 blo = pb[0], bhi = pb[1];
            bl[0]=blo.x; bl[1]=blo.y; bl[2]=blo.z; bl[3]=blo.w;
            bh[0]=bhi.x; bh[1]=bhi.y; bh[2]=bhi.z; bh[3]=bhi.w;
        } else {
            #pragma unroll
            for (int j=0;j<4;j++) { bl[j]=0u; bh[j]=0u; }
        }
    }

    const int NTILES = NQ / KT;   // 50
    for (int it = 0; it < NTILES; ++it) {
        char* base = smx + (it & 1) * 16384;
        char* Asl = base;
        char* Bsl = base + 8192;

        {
            char* aw = Asl + ((ps*8 + pmt)*32 + pgA*4) * 16 + hwA;
            char* bw = Bsl + ((ps*16 + pnt)*32 + pgB*4) * 8;
            #pragma unroll
            for (int j = 0; j < 4; ++j) {
                *(uint2*)(aw + j*16) = make_uint2(al[j], ah[j]);
                *(uint2*)(bw + j*8)  = make_uint2(bl[j], bh[j]);
            }
        }
        __syncthreads();

        if (it + 1 < NTILES) {
            int k0n = (it + 1) * KT;
            const uint4* pa = (const uint4*)(Gm + (size_t)(m0+prow)*NQ + k0n + ps*16);
            uint4 lo = pa[0], hi = pa[1];
            al[0]=lo.x; al[1]=lo.y; al[2]=lo.z; al[3]=lo.w;
            ah[0]=hi.x; ah[1]=hi.y; ah[2]=hi.z; ah[3]=hi.w;
            if (pBvalid) {
                const uint4* pb = (const uint4*)(Bm + (size_t)(n0+prow)*NQ + k0n + ps*16);
                uint4 blo = pb[0], bhi = pb[1];
                bl[0]=blo.x; bl[1]=blo.y; bl[2]=blo.z; bl[3]=blo.w;
                bh[0]=bhi.x; bh[1]=bhi.y; bh[2]=bhi.z; bh[3]=bhi.w;
            }
        }

        #pragma unroll
        for (int s = 0; s < 2; ++s) {
            uint4 af[4]; uint2 bf[4];
            #pragma unroll
            for (int mt = 0; mt < 4; ++mt)
                af[mt] = *(const uint4*)(Asl + (((s*8 + wm*4 + mt)*32 + lane) * 16));
            #pragma unroll
            for (int nt = 0; nt < 4; ++nt)
                bf[nt] = *(const uint2*)(Bsl + (((s*16 + wn*4 + nt)*32 + lane) * 8));
            #pragma unroll
            for (int mt = 0; mt < 4; ++mt)
                #pragma unroll
                for (int nt = 0; nt < 4; ++nt)
                    mma_f16(acc[mt][nt], af[mt].x, af[mt].z, af[mt].y, af[mt].w,
                            bf[nt].x, bf[nt].y);
        }
    }

    #pragma unroll
    for (int mt = 0; mt < 4; ++mt) {
        int m = m0 + wm*64 + mt*16 + (lane >> 2);
        #pragma unroll
        for (int nt = 0; nt < 4; ++nt) {
            int n = n0 + wn*32 + nt*8 + 2*(lane & 3);
            if (n < NQ) {
                *(float2*)&Tm[(size_t)m*NQ + n]     = make_float2(acc[mt][nt][0], acc[mt][nt][1]);
                *(float2*)&Tm[(size_t)(m+8)*NQ + n] = make_float2(acc[mt][nt][2], acc[mt][nt][3]);
            }
        }
    }
}

// ------------- gather epilogue + cosine-window blend -> output (2,128,80,80)
__global__ void k_combine(float* __restrict__ out) {
    int idx = blockIdx.x*blockDim.x + threadIdx.x;
    const int total = NB*NC*FH*FW;
    if (idx >= total) return;
    int X = idx % FW; int t = idx / FW;
    int Y = t % FH; t /= FH;
    int c = t % NC; int b = t / NC;

    int dys[2], hh[2]; int ny = 0;
    if ((Y & 1) == 0) {
        dys[ny] = 0; hh[ny] = Y >> 1; ny++;
        if (Y >= 2) { dys[ny] = 2; hh[ny] = (Y-2) >> 1; ny++; }
    } else {
        dys[ny] = 1; hh[ny] = (Y-1) >> 1; ny++;
        if (Y <= 2*HS - 3) { dys[ny] = -1; hh[ny] = (Y+1) >> 1; ny++; }
    }
    int dxs[2], ww[2]; int nx = 0;
    if ((X & 1) == 0) {
        dxs[nx] = 0; ww[nx] = X >> 1; nx++;
        if (X >= 2) { dxs[nx] = 2; ww[nx] = (X-2) >> 1; nx++; }
    } else {
        dxs[nx] = 1; ww[nx] = (X-1) >> 1; nx++;
        if (X <= 2*HS - 3) { dxs[nx] = -1; ww[nx] = (X+1) >> 1; nx++; }
    }

    const float PI = 3.14159265358979323846f;
    float wl = 0.5f*(1.f + cosf(PI * (float)X        / (float)(FW-1)));
    float wr = 0.5f*(1.f + cosf(PI * (float)(FW-1-X) / (float)(FW-1)));

    float res = 0.f;
    for (int s = 0; s < 2; ++s) {
        const float* T = g_T + (size_t)(b*2 + s)*MROWS*NQ;
        float acc = 0.f;
        for (int iy = 0; iy < ny; ++iy) {
            for (int ix = 0; ix < nx; ++ix) {
                int m = c*16 + (dys[iy]+1)*4 + (dxs[ix]+1);
                acc += T[(size_t)m*NQ + hh[iy]*HS + ww[ix]];
            }
        }
        res += (s == 0 ? wl : wr) * 0.25f * acc;
    }
    out[idx] = res;
}

// ------------------------------------------------------------------ launcher
extern "C" void kernel_launch(void* const* d_in, const int* in_sizes, int n_in,
                              void* d_out, int out_size) {
    const float* left      = (const float*)d_in[0];
    const float* right     = (const float*)d_in[1];
    const float* mid       = (const float*)d_in[2];
    const float* raw_left  = (const float*)d_in[3];
    const float* raw_right = (const float*)d_in[4];
    float* outp = (float*)d_out;

    cudaFuncSetAttribute(k_gemm2h, cudaFuncAttributeMaxDynamicSharedMemorySize, G2_SMEM);

    int t1 = NB*3*NC*NQ;
    k_downsample<<<(t1+255)/256, 256>>>(left, right, mid);
    int t2 = NB*2*NQ;
    k_sumsq<<<(t2+127)/128, 128>>>();
    k_norm<<<(t2+127)/128, 128>>>();

    dim3 g1(NQ/64, NQ/64, NB*2);     // 25 x 25 x 4
    k_gemm1<<<g1, 256>>>();

    int tp4 = NB*2*NQ*(NQ/4);
    k_psfuse<<<(tp4+255)/256, 256>>>();

    k_softmax_stats<<<dim3(NQ/64, NB*2), 256>>>();
    k_attnT<<<dim3(NQ/32, NQ/32, NB*2), dim3(32, 8)>>>();

    int tg8 = NB*2*MROWS*(NQ/8);
    k_buildG<<<(tg8+255)/256, 256>>>(raw_left, raw_right);

    dim3 g2(MROWS/128, (NQ+127)/128, NB*2);   // 16 x 13 x 4
    k_gemm2h<<<g2, 256, G2_SMEM>>>();

    int to = NB*NC*FH*FW;
    k_combine<<<(to+255)/256, 256>>>(outp);
}

// round 7
// speedup vs baseline: 1.1556x; 1.1556x over previous
#include <cuda_runtime.h>
#include <cuda_fp16.h>
#include <math.h>
#include <stdint.h>

// Problem constants
#define NB 2
#define NC 128
#define FH 80
#define FW 80
#define HS 40            // downsampled H=W
#define NQ 1600          // HS*HS
#define NEPS 0.1152f     // 1152 * EPS
#define SCL 10.0f
#define MROWS 2048       // NC * 16 offsets

// fp16 mma GEMM2 config: CTA 128x128, K-tile 32 halfs, 8 warps (warp tile 64x32)
#define KT 32
#define G2_SMEM 32768    // 2 buffers x (8KB A + 8KB B)

// Static scratch (allocation-free rule: __device__ globals)
__device__ float  g_ds[NB*3*NC*NQ];          // downsampled [b][img: 0=l,1=r,2=m][c][q]
__device__ float  g_E[NB*2*NQ];              // per-pixel channel sum of squares (l, r)
__device__ float  g_ninv[NB*2*NQ];           // 1/patch-norm
__device__ float  g_smax[NB*2*NQ];           // softmax max per (bs,p)
__device__ float  g_sinv[NB*2*NQ];           // softmax 1/sum per (bs,p)
__device__ float  g_bufA[NB*2*NQ*NQ];        // 41.9 MB (pixcorr / final scores)
__device__ float  g_bufB[NB*2*NQ*NQ];        // 41.9 MB (post-psfuse scores)
__device__ __align__(16) __half g_Gh[NB*2*MROWS*NQ];   // 26 MB paste operand [bs][m][q]
__device__ __align__(16) __half g_ATh[NB*2*NQ*NQ];     // 20.5 MB attnT [bs][p][q]
__device__ float  g_T[NB*2*MROWS*NQ];        // 52.4 MB paste result [bs][m][p]

// ---------------------------------------------------------------- downsample
__global__ void k_downsample(const float* __restrict__ left,
                             const float* __restrict__ right,
                             const float* __restrict__ mid) {
    int idx = blockIdx.x * blockDim.x + threadIdx.x;
    const int total = NB*3*NC*NQ;
    if (idx >= total) return;
    int q = idx % NQ;
    int t = idx / NQ;
    int c = t % NC; t /= NC;
    int img = t % 3; int b = t / 3;
    const float* src = (img == 0) ? left : (img == 1 ? right : mid);
    int qh = q / HS, qw = q % HS;
    g_ds[idx] = src[(size_t)((b*NC + c)*FH + 2*qh)*FW + 2*qw];
}

// ------------------------------------------------- channel sum-of-squares (l,r)
__global__ void k_sumsq() {
    int idx = blockIdx.x*blockDim.x + threadIdx.x;
    const int total = NB*2*NQ;
    if (idx >= total) return;
    int q = idx % NQ; int t = idx / NQ;
    int s = t % 2; int b = t / 2;
    const float* p = g_ds + (size_t)(b*3 + s)*NC*NQ + q;
    float acc = 0.f;
    #pragma unroll 8
    for (int c = 0; c < NC; ++c) { float v = p[(size_t)c*NQ]; acc += v*v; }
    g_E[idx] = acc;
}

// -------------------------------------------------- patch norm
__global__ void k_norm() {
    int idx = blockIdx.x*blockDim.x + threadIdx.x;
    const int total = NB*2*NQ;
    if (idx >= total) return;
    int q = idx % NQ; int bs = idx / NQ;
    int qh = q/HS, qw = q%HS;
    float acc = NEPS;
    for (int di=-1; di<=1; ++di) {
        int h = qh+di; if (h < 0 || h >= HS) continue;
        for (int dj=-1; dj<=1; ++dj) {
            int w = qw+dj; if (w < 0 || w >= HS) continue;
            acc += g_E[bs*NQ + h*HS + w];
        }
    }
    g_ninv[idx] = rsqrtf(acc);
}

// ----------------------------- GEMM1 (fp32): PixCorr[q,p] = sum_c L[c,q]*M[c,p]
__global__ void k_gemm1() {
    int bs = blockIdx.z;
    int b = bs >> 1, s = bs & 1;
    const float* A  = g_ds + (size_t)(b*3 + s)*NC*NQ;
    const float* Bm = g_ds + (size_t)(b*3 + 2)*NC*NQ;
    float* Cout = g_bufA + (size_t)bs*NQ*NQ;
    __shared__ float As[16][64];
    __shared__ float Bs[16][64];
    int tx = threadIdx.x;
    int m0 = blockIdx.x*64, n0 = blockIdx.y*64;
    int lk = tx >> 4, lm = (tx & 15) * 4;
    int lr = tx >> 4, lc = tx & 15;
    float acc[4][4];
    #pragma unroll
    for (int i=0;i<4;i++)
        #pragma unroll
        for (int j=0;j<4;j++) acc[i][j] = 0.f;
    for (int k0 = 0; k0 < NC; k0 += 16) {
        *(float4*)&As[lk][lm] = *(const float4*)&A [(size_t)(k0+lk)*NQ + m0 + lm];
        *(float4*)&Bs[lk][lm] = *(const float4*)&Bm[(size_t)(k0+lk)*NQ + n0 + lm];
        __syncthreads();
        #pragma unroll
        for (int kk = 0; kk < 16; ++kk) {
            float4 av = *(const float4*)&As[kk][lr*4];
            float4 bv = *(const float4*)&Bs[kk][lc*4];
            float a[4] = {av.x, av.y, av.z, av.w};
            float bb[4] = {bv.x, bv.y, bv.z, bv.w};
            #pragma unroll
            for (int i=0;i<4;i++)
                #pragma unroll
                for (int j=0;j<4;j++) acc[i][j] += a[i]*bb[j];
        }
        __syncthreads();
    }
    #pragma unroll
    for (int i=0;i<4;i++) {
        float4 v = make_float4(acc[i][0],acc[i][1],acc[i][2],acc[i][3]);
        *(float4*)&Cout[(size_t)(m0+lr*4+i)*NQ + n0 + lc*4] = v;
    }
}

// -------- FUSED patchsum + fuse1, 4 outputs per thread (bufA -> bufB)
__global__ void k_psfuse() {
    int idx = blockIdx.x*blockDim.x + threadIdx.x;
    const int total4 = NB*2*NQ*(NQ/4);
    if (idx >= total4) return;
    int p4 = (idx % (NQ/4)) * 4;
    int t = idx / (NQ/4);
    int q = t % NQ;
    int bs = t / NQ;
    const float* __restrict__ Cm = g_bufA + (size_t)bs*NQ*NQ;
    const float* __restrict__ ninv = g_ninv + bs*NQ;
    const int qh = q/HS, qw = q - (q/HS)*HS;
    const int ph0 = p4/HS, pw0 = p4 - (p4/HS)*HS;   // pw0 in [0,36], 4-aligned
    float acc[4] = {0.f,0.f,0.f,0.f};

    #pragma unroll
    for (int ei = 0; ei < 3; ++ei) {
        const int e = (ei==0) ? 0 : (ei==1 ? -1 : 1);
        const int Q = q + e;
        if (Q < 0 || Q >= NQ) continue;
        int Qh = qh, Qw = qw + e;
        if (Qw < 0) { Qh -= 1; Qw = HS-1; }
        else if (Qw >= HS) { Qh += 1; Qw = 0; }
        const float nv = ninv[Q];
        int Pj[4], Phj[4], Pwj[4]; bool Vj[4];
        #pragma unroll
        for (int j = 0; j < 4; ++j) {
            int P = p4 + e + j;
            int Pw = pw0 + e + j, Ph = ph0;
            if (Pw < 0) { Ph -= 1; Pw = HS-1; }
            else if (Pw >= HS) { Ph += 1; Pw = 0; }
            Pj[j] = P; Phj[j] = Ph; Pwj[j] = Pw;
            Vj[j] = (P >= 0) && (P < NQ);
        }
        float ps[4] = {0.f,0.f,0.f,0.f};
        #pragma unroll
        for (int di = -1; di <= 1; ++di) {
            int Qhd = Qh + di;
            if (Qhd < 0 || Qhd >= HS) continue;
            #pragma unroll
            for (int dj = -1; dj <= 1; ++dj) {
                int Qwd = Qw + dj;
                if (Qwd < 0 || Qwd >= HS) continue;
                int sh = di*HS + dj;
                const float* row = Cm + (size_t)(Q + sh)*NQ;
                #pragma unroll
                for (int j = 0; j < 4; ++j) {
                    int Phd = Phj[j] + di, Pwd = Pwj[j] + dj;
                    if (Vj[j] && Phd >= 0 && Phd < HS && Pwd >= 0 && Pwd < HS)
                        ps[j] += row[Pj[j] + sh];
                }
            }
        }
        #pragma unroll
        for (int j = 0; j < 4; ++j) acc[j] += ps[j] * nv;
    }
    *(float4*)&g_bufB[((size_t)(bs*NQ + q))*NQ + p4] =
        make_float4(acc[0], acc[1], acc[2], acc[3]);
}

// ---------------- fuse pass 2 (bufB -> bufA), 4 outputs per thread
// taps: out[q][p] = F[q][p] (+ F[qm][pm] if q>0&&p>0) (+ F[qp][pp] if q<NQ-1&&p<NQ-1)
// where xm = tflat(tflat(x)-1) = (xh>0) ? x-HS : (HS-1)*HS + xw-1
//       xp = tflat(tflat(x)+1) = (xh<HS-1) ? x+HS : xw+1
// For a 4-aligned p-block both branches yield 4 contiguous indices.
__global__ void k_fuse2() {
    int idx = blockIdx.x*blockDim.x + threadIdx.x;
    const int total4 = NB*2*NQ*(NQ/4);
    if (idx >= total4) return;
    int p4 = (idx % (NQ/4)) * 4;
    int t = idx / (NQ/4);
    int q = t % NQ;
    int bs = t / NQ;
    const float* __restrict__ F = g_bufB + (size_t)bs*NQ*NQ;
    const int qh = q/HS, qw = q - (q/HS)*HS;
    const int ph = p4/HS, pw0 = p4 - (p4/HS)*HS;

    float acc[4];
    *(float4*)acc = *(const float4*)&F[(size_t)q*NQ + p4];

    if (q > 0) {
        const int qm = (qh > 0) ? (q - HS) : ((HS-1)*HS + qw - 1);
        const int pmb = (ph > 0) ? (p4 - HS) : ((HS-1)*HS + pw0 - 1);
        const float* rowm = F + (size_t)qm*NQ;
        #pragma unroll
        for (int j = 0; j < 4; ++j)
            if (p4 + j > 0) acc[j] += rowm[pmb + j];
    }
    if (q < NQ-1) {
        const int qp = (qh < HS-1) ? (q + HS) : (qw + 1);
        const int ppb = (ph < HS-1) ? (p4 + HS) : (pw0 + 1);
        const float* rowp = F + (size_t)qp*NQ;
        #pragma unroll
        for (int j = 0; j < 4; ++j)
            if (p4 + j < NQ-1) acc[j] += rowp[ppb + j];
    }
    *(float4*)&g_bufA[((size_t)(bs*NQ + q))*NQ + p4] = *(float4*)acc;
}

// --------------- softmax stats: per (bs,p) max over q and 1/sum(exp) (reads bufA)
__global__ void k_softmax_stats() {
    int bs = blockIdx.y;
    int p0 = blockIdx.x * 64;
    const float* __restrict__ F = g_bufA + (size_t)bs*NQ*NQ;
    int px = threadIdx.x & 63;
    int qy = threadIdx.x >> 6;        // 0..3
    int p = p0 + px;
    __shared__ float red[4][64];
    float mx = -3.4e38f;
    for (int q = qy; q < NQ; q += 4) mx = fmaxf(mx, F[(size_t)q*NQ + p]);
    red[qy][px] = mx;
    __syncthreads();
    mx = fmaxf(fmaxf(red[0][px], red[1][px]), fmaxf(red[2][px], red[3][px]));
    __syncthreads();
    float sm = 0.f;
    for (int q = qy; q < NQ; q += 4) sm += __expf(SCL * (F[(size_t)q*NQ + p] - mx));
    red[qy][px] = sm;
    __syncthreads();
    if (qy == 0) {
        g_smax[bs*NQ + p] = mx;
        g_sinv[bs*NQ + p] = 1.0f / (red[0][px] + red[1][px] + red[2][px] + red[3][px]);
    }
}

// --------------- attnT: transposed, normalized attn as half (bufA -> g_ATh)
__global__ void k_attnT() {
    __shared__ float tile[32][33];
    int bs = blockIdx.z;
    int q0 = blockIdx.x * 32, p0 = blockIdx.y * 32;
    const float* __restrict__ F = g_bufA + (size_t)bs*NQ*NQ;
    __half* __restrict__ O = g_ATh + (size_t)bs*NQ*NQ;
    int tx = threadIdx.x, ty = threadIdx.y;  // 32 x 8
    for (int r = ty; r < 32; r += 8)
        tile[r][tx] = F[(size_t)(q0+r)*NQ + p0 + tx];
    __syncthreads();
    for (int r = ty; r < 32; r += 8) {
        int p = p0 + r;
        float e = __expf(SCL * (tile[tx][r] - g_smax[bs*NQ + p])) * g_sinv[bs*NQ + p];
        O[(size_t)p*NQ + q0 + tx] = __float2half_rn(e);
    }
}

// --------------- build paste operand G[bs][m][q] as half, 8 q per thread
__global__ void k_buildG(const float* __restrict__ raw_left,
                         const float* __restrict__ raw_right) {
    int idx = blockIdx.x*blockDim.x + threadIdx.x;
    const int total8 = NB*2*MROWS*(NQ/8);
    if (idx >= total8) return;
    int q8 = (idx % (NQ/8)) * 8;
    int t = idx / (NQ/8);
    int m = t % MROWS;
    int bs = t / MROWS;
    int b = bs >> 1, s = bs & 1;
    int c = m >> 4;
    int o = m & 15;
    int dy = (o >> 2) - 1, dx = (o & 3) - 1;
    int qh = q8 / HS, qw0 = q8 - (q8/HS)*HS;
    int y = 2*qh + dy;
    const float* raw = (s ? raw_right : raw_left) + (size_t)(b*NC + c)*FH*FW;
    __half hv[8];
    if (y >= 0 && y < FH) {
        const float* rrow = raw + (size_t)y*FW;
        #pragma unroll
        for (int j = 0; j < 8; ++j) {
            int x = 2*(qw0 + j) + dx;
            hv[j] = (x >= 0 && x < FW) ? __float2half_rn(rrow[x]) : __half(0.f);
        }
    } else {
        #pragma unroll
        for (int j = 0; j < 8; ++j) hv[j] = __half(0.f);
    }
    *(uint4*)&g_Gh[(size_t)(bs*MROWS + m)*NQ + q8] = *(uint4*)hv;
}

// ------------- GEMM2 (mma.sync fp16, f32 accum): T[m,p] = sum_q G[m,q] * attnT[p,q]
__device__ __forceinline__ void mma_f16(float* c, uint32_t a0, uint32_t a1,
                                        uint32_t a2, uint32_t a3,
                                        uint32_t b0, uint32_t b1) {
    asm volatile(
        "mma.sync.aligned.m16n8k16.row.col.f32.f16.f16.f32 "
        "{%0,%1,%2,%3}, {%4,%5,%6,%7}, {%8,%9}, {%0,%1,%2,%3};"
        : "+f"(c[0]), "+f"(c[1]), "+f"(c[2]), "+f"(c[3])
        : "r"(a0), "r"(a1), "r"(a2), "r"(a3), "r"(b0), "r"(b1));
}

__global__ void __launch_bounds__(256) k_gemm2h() {
    extern __shared__ char smx[];
    const int bs = blockIdx.z;
    const __half* __restrict__ Gm = g_Gh  + (size_t)bs*MROWS*NQ;   // [m][q]
    const __half* __restrict__ Bm = g_ATh + (size_t)bs*NQ*NQ;      // [p][q]
    float* __restrict__ Tm = g_T + (size_t)bs*MROWS*NQ;
    const int m0 = blockIdx.x * 128, n0 = blockIdx.y * 128;
    const int t = threadIdx.x;
    const int lane = t & 31, wid = t >> 5;
    const int wm = wid & 1, wn = wid >> 1;      // warp grid 2(m) x 4(n)

    const int prow = t >> 1, ps = t & 1;
    const int pmt = prow >> 4, prr = prow & 15;
    const int pgA = prr & 7;
    const int hwA = (prr >> 3) << 3;
    const int pnt = prow >> 3, pgB = prow & 7;
    const bool pBvalid = (n0 + prow) < NQ;

    uint32_t al[4], ah[4], bl[4], bh[4];

    float acc[4][4][4];
    #pragma unroll
    for (int i=0;i<4;i++)
        #pragma unroll
        for (int j=0;j<4;j++)
            #pragma unroll
            for (int k=0;k<4;k++) acc[i][j][k] = 0.f;

    {
        const uint4* pa = (const uint4*)(Gm + (size_t)(m0+prow)*NQ + ps*16);
        uint4 lo = pa[0], hi = pa[1];
        al[0]=lo.x; al[1]=lo.y; al[2]=lo.z; al[3]=lo.w;
        ah[0]=hi.x; ah[1]=hi.y; ah[2]=hi.z; ah[3]=hi.w;
        if (pBvalid) {
            const uint4* pb = (const uint4*)(Bm + (size_t)(n0+prow)*NQ + ps*16);
            uint4 blo = pb[0], bhi = pb[1];
            bl[0]=blo.x; bl[1]=blo.y; bl[2]=blo.z; bl[3]=blo.w;
            bh[0]=bhi.x; bh[1]=bhi.y; bh[2]=bhi.z; bh[3]=bhi.w;
        } else {
            #pragma unroll
            for (int j=0;j<4;j++) { bl[j]=0u; bh[j]=0u; }
        }
    }

    const int NTILES = NQ / KT;   // 50
    for (int it = 0; it < NTILES; ++it) {
        char* base = smx + (it & 1) * 16384;
        char* Asl = base;
        char* Bsl = base + 8192;

        {
            char* aw = Asl + ((ps*8 + pmt)*32 + pgA*4) * 16 + hwA;
            char* bw = Bsl + ((ps*16 + pnt)*32 + pgB*4) * 8;
            #pragma unroll
            for (int j = 0; j < 4; ++j) {
                *(uint2*)(aw + j*16) = make_uint2(al[j], ah[j]);
                *(uint2*)(bw + j*8)  = make_uint2(bl[j], bh[j]);
            }
        }
        __syncthreads();

        if (it + 1 < NTILES) {
            int k0n = (it + 1) * KT;
            const uint4* pa = (const uint4*)(Gm + (size_t)(m0+prow)*NQ + k0n + ps*16);
            uint4 lo = pa[0], hi = pa[1];
            al[0]=lo.x; al[1]=lo.y; al[2]=lo.z; al[3]=lo.w;
            ah[0]=hi.x; ah[1]=hi.y; ah[2]=hi.z; ah[3]=hi.w;
            if (pBvalid) {
                const uint4* pb = (const uint4*)(Bm + (size_t)(n0+prow)*NQ + k0n + ps*16);
                uint4 blo = pb[0], bhi = pb[1];
                bl[0]=blo.x; bl[1]=blo.y; bl[2]=blo.z; bl[3]=blo.w;
                bh[0]=bhi.x; bh[1]=bhi.y; bh[2]=bhi.z; bh[3]=bhi.w;
            }
        }

        #pragma unroll
        for (int s = 0; s < 2; ++s) {
            uint4 af[4]; uint2 bf[4];
            #pragma unroll
            for (int mt = 0; mt < 4; ++mt)
                af[mt] = *(const uint4*)(Asl + (((s*8 + wm*4 + mt)*32 + lane) * 16));
            #pragma unroll
            for (int nt = 0; nt < 4; ++nt)
                bf[nt] = *(const uint2*)(Bsl + (((s*16 + wn*4 + nt)*32 + lane) * 8));
            #pragma unroll
            for (int mt = 0; mt < 4; ++mt)
                #pragma unroll
                for (int nt = 0; nt < 4; ++nt)
                    mma_f16(acc[mt][nt], af[mt].x, af[mt].z, af[mt].y, af[mt].w,
                            bf[nt].x, bf[nt].y);
        }
    }

    #pragma unroll
    for (int mt = 0; mt < 4; ++mt) {
        int m = m0 + wm*64 + mt*16 + (lane >> 2);
        #pragma unroll
        for (int nt = 0; nt < 4; ++nt) {
            int n = n0 + wn*32 + nt*8 + 2*(lane & 3);
            if (n < NQ) {
                *(float2*)&Tm[(size_t)m*NQ + n]     = make_float2(acc[mt][nt][0], acc[mt][nt][1]);
                *(float2*)&Tm[(size_t)(m+8)*NQ + n] = make_float2(acc[mt][nt][2], acc[mt][nt][3]);
            }
        }
    }
}

// ------------- gather epilogue + cosine-window blend -> output (2,128,80,80)
__global__ void k_combine(float* __restrict__ out) {
    int idx = blockIdx.x*blockDim.x + threadIdx.x;
    const int total = NB*NC*FH*FW;
    if (idx >= total) return;
    int X = idx % FW; int t = idx / FW;
    int Y = t % FH; t /= FH;
    int c = t % NC; int b = t / NC;

    int dys[2], hh[2]; int ny = 0;
    if ((Y & 1) == 0) {
        dys[ny] = 0; hh[ny] = Y >> 1; ny++;
        if (Y >= 2) { dys[ny] = 2; hh[ny] = (Y-2) >> 1; ny++; }
    } else {
        dys[ny] = 1; hh[ny] = (Y-1) >> 1; ny++;
        if (Y <= 2*HS - 3) { dys[ny] = -1; hh[ny] = (Y+1) >> 1; ny++; }
    }
    int dxs[2], ww[2]; int nx = 0;
    if ((X & 1) == 0) {
        dxs[nx] = 0; ww[nx] = X >> 1; nx++;
        if (X >= 2) { dxs[nx] = 2; ww[nx] = (X-2) >> 1; nx++; }
    } else {
        dxs[nx] = 1; ww[nx] = (X-1) >> 1; nx++;
        if (X <= 2*HS - 3) { dxs[nx] = -1; ww[nx] = (X+1) >> 1; nx++; }
    }

    const float PI = 3.14159265358979323846f;
    float wl = 0.5f*(1.f + cosf(PI * (float)X        / (float)(FW-1)));
    float wr = 0.5f*(1.f + cosf(PI * (float)(FW-1-X) / (float)(FW-1)));

    float res = 0.f;
    for (int s = 0; s < 2; ++s) {
        const float* T = g_T + (size_t)(b*2 + s)*MROWS*NQ;
        float acc = 0.f;
        for (int iy = 0; iy < ny; ++iy) {
            for (int ix = 0; ix < nx; ++ix) {
                int m = c*16 + (dys[iy]+1)*4 + (dxs[ix]+1);
                acc += T[(size_t)m*NQ + hh[iy]*HS + ww[ix]];
            }
        }
        res += (s == 0 ? wl : wr) * 0.25f * acc;
    }
    out[idx] = res;
}

// ------------------------------------------------------------------ launcher
extern "C" void kernel_launch(void* const* d_in, const int* in_sizes, int n_in,
                              void* d_out, int out_size) {
    const float* left      = (const float*)d_in[0];
    const float* right     = (const float*)d_in[1];
    const float* mid       = (const float*)d_in[2];
    const float* raw_left  = (const float*)d_in[3];
    const float* raw_right = (const float*)d_in[4];
    float* outp = (float*)d_out;

    cudaFuncSetAttribute(k_gemm2h, cudaFuncAttributeMaxDynamicSharedMemorySize, G2_SMEM);

    int t1 = NB*3*NC*NQ;
    k_downsample<<<(t1+255)/256, 256>>>(left, right, mid);
    int t2 = NB*2*NQ;
    k_sumsq<<<(t2+127)/128, 128>>>();
    k_norm<<<(t2+127)/128, 128>>>();

    dim3 g1(NQ/64, NQ/64, NB*2);     // 25 x 25 x 4
    k_gemm1<<<g1, 256>>>();

    int tp4 = NB*2*NQ*(NQ/4);
    k_psfuse<<<(tp4+255)/256, 256>>>();
    k_fuse2<<<(tp4+255)/256, 256>>>();

    k_softmax_stats<<<dim3(NQ/64, NB*2), 256>>>();
    k_attnT<<<dim3(NQ/32, NQ/32, NB*2), dim3(32, 8)>>>();

    int tg8 = NB*2*MROWS*(NQ/8);
    k_buildG<<<(tg8+255)/256, 256>>>(raw_left, raw_right);

    dim3 g2(MROWS/128, (NQ+127)/128, NB*2);   // 16 x 13 x 4
    k_gemm2h<<<g2, 256, G2_SMEM>>>();

    int to = NB*NC*FH*FW;
    k_combine<<<(to+255)/256, 256>>>(outp);
}